// round 15
// baseline (speedup 1.0000x reference)
#include <cuda_runtime.h>
#include <cuda_bf16.h>
#include <math.h>
#include <cstdint>

#define L_TOTAL 2048
#define D_MODEL 2048
#define D_HEAD  128
#define N_HEADS 16
#define QKV_COLS (3 * D_MODEL)   // 6144
#define EPS 1e-6f
#define SM_SCALE 0.08838834764831845f   // 1/sqrt(128)

// ---------------- scratch (device globals: allocation-free rule) ------------
__device__ float g_qkv[(size_t)L_TOTAL * QKV_COLS];   // [L, 6144] = q|k|v (fp32)

__device__ __nv_bfloat16 g_xhi[(size_t)L_TOTAL * D_MODEL];
__device__ __nv_bfloat16 g_xlo[(size_t)L_TOTAL * D_MODEL];
__device__ __nv_bfloat16 g_wqkv_hi[(size_t)QKV_COLS * D_MODEL];
__device__ __nv_bfloat16 g_wqkv_lo[(size_t)QKV_COLS * D_MODEL];
__device__ __nv_bfloat16 g_wp_hi[(size_t)D_MODEL * D_MODEL];
__device__ __nv_bfloat16 g_wp_lo[(size_t)D_MODEL * D_MODEL];
__device__ __nv_bfloat16 g_ahi[(size_t)L_TOTAL * D_MODEL];
__device__ __nv_bfloat16 g_alo[(size_t)L_TOTAL * D_MODEL];

// =================== helpers ================================================
__device__ __forceinline__ uint32_t smem_to_u32(const void* p) {
    uint32_t a;
    asm("{ .reg .u64 t; cvta.to.shared.u64 t, %1; cvt.u32.u64 %0, t; }"
        : "=r"(a) : "l"(p));
    return a;
}

__device__ __forceinline__ void ldsm_x4(uint32_t* r, uint32_t addr) {
    asm volatile("ldmatrix.sync.aligned.m8n8.x4.shared.b16 {%0,%1,%2,%3}, [%4];"
                 : "=r"(r[0]), "=r"(r[1]), "=r"(r[2]), "=r"(r[3]) : "r"(addr));
}

__device__ __forceinline__ void mma_bf16(float* c, const uint32_t* a,
                                         uint32_t b0, uint32_t b1) {
    asm volatile(
        "mma.sync.aligned.m16n8k16.row.col.f32.bf16.bf16.f32 "
        "{%0,%1,%2,%3}, {%4,%5,%6,%7}, {%8,%9}, {%0,%1,%2,%3};\n"
        : "+f"(c[0]), "+f"(c[1]), "+f"(c[2]), "+f"(c[3])
        : "r"(a[0]), "r"(a[1]), "r"(a[2]), "r"(a[3]), "r"(b0), "r"(b1));
}

__device__ __forceinline__ void cp16(uint32_t saddr, const void* gaddr) {
    asm volatile("cp.async.cg.shared.global [%0], [%1], 16;"
                 :: "r"(saddr), "l"(gaddr));
}
#define CP_COMMIT() asm volatile("cp.async.commit_group;" ::: "memory")
#define CP_WAIT0()  asm volatile("cp.async.wait_group 0;" ::: "memory")

// =================== split fp32 -> bf16 hi + bf16 lo ========================
__global__ __launch_bounds__(256) void split_bf16_kernel(
    const float* __restrict__ src,
    __nv_bfloat16* __restrict__ hi, __nv_bfloat16* __restrict__ lo, int n4)
{
    const int i = blockIdx.x * 256 + threadIdx.x;
    if (i >= n4) return;
    const float4 v = ((const float4*)src)[i];
    __nv_bfloat16 h0 = __float2bfloat16(v.x);
    __nv_bfloat16 h1 = __float2bfloat16(v.y);
    __nv_bfloat16 h2 = __float2bfloat16(v.z);
    __nv_bfloat16 h3 = __float2bfloat16(v.w);
    __nv_bfloat16 l0 = __float2bfloat16(v.x - __bfloat162float(h0));
    __nv_bfloat16 l1 = __float2bfloat16(v.y - __bfloat162float(h1));
    __nv_bfloat16 l2 = __float2bfloat16(v.z - __bfloat162float(h2));
    __nv_bfloat16 l3 = __float2bfloat16(v.w - __bfloat162float(h3));
    __nv_bfloat162 hp0; hp0.x = h0; hp0.y = h1;
    __nv_bfloat162 hp1; hp1.x = h2; hp1.y = h3;
    __nv_bfloat162 lp0; lp0.x = l0; lp0.y = l1;
    __nv_bfloat162 lp1; lp1.x = l2; lp1.y = l3;
    ((__nv_bfloat162*)hi)[2 * i]     = hp0;
    ((__nv_bfloat162*)hi)[2 * i + 1] = hp1;
    ((__nv_bfloat162*)lo)[2 * i]     = lp0;
    ((__nv_bfloat162*)lo)[2 * i + 1] = lp1;
}

// =================== HMMA split-bf16 GEMM (cp.async 2-stage, 2 CTA/SM) ======
#define SMS 80
#define MATB (128 * SMS)
#define STAGEB (4 * MATB)
#define NSTAGE 2
#define GEMM_SMEM (NSTAGE * STAGEB)  // 81920 B

__global__ __launch_bounds__(256, 2) void gemm_mma(
    const __nv_bfloat16* __restrict__ Ahi, const __nv_bfloat16* __restrict__ Alo,
    const __nv_bfloat16* __restrict__ Bhi, const __nv_bfloat16* __restrict__ Blo,
    const float* __restrict__ bias, float* __restrict__ C, int N, int K)
{
    extern __shared__ __align__(16) char sm[];

    const int tid = threadIdx.x;
    const int lane = tid & 31, wid = tid >> 5;
    const int warp_m = wid >> 2, warp_n = wid & 3;
    const int m0 = blockIdx.y * 128, n0 = blockIdx.x * 128;

    const __nv_bfloat16* srcs[4];
    srcs[0] = Ahi + (size_t)m0 * K;
    srcs[1] = Alo + (size_t)m0 * K;
    srcs[2] = Bhi + (size_t)n0 * K;
    srcs[3] = Blo + (size_t)n0 * K;

    const int r_lo = tid >> 2,          q_lo = tid & 3;
    const int r_hi = (tid + 256) >> 2,  q_hi = tid & 3;

    const uint32_t sbase = smem_to_u32(sm);

    float acc[4][4][4];
    #pragma unroll
    for (int a = 0; a < 4; ++a)
        #pragma unroll
        for (int b = 0; b < 4; ++b)
            #pragma unroll
            for (int cc = 0; cc < 4; ++cc) acc[a][b][cc] = 0.f;

    const int lrow = lane & 15;
    const int lcol = (lane >> 4) * 16;
    uint32_t aAddrH[4], aAddrL[4], bAddrH[2], bAddrL[2];
    #pragma unroll
    for (int mf = 0; mf < 4; ++mf) {
        const int r = warp_m * 64 + mf * 16 + lrow;
        aAddrH[mf] = sbase + 0 * MATB + r * SMS + lcol;
        aAddrL[mf] = sbase + 1 * MATB + r * SMS + lcol;
    }
    #pragma unroll
    for (int np = 0; np < 2; ++np) {
        const int r = warp_n * 32 + np * 16 + lrow;
        bAddrH[np] = sbase + 2 * MATB + r * SMS + lcol;
        bAddrL[np] = sbase + 3 * MATB + r * SMS + lcol;
    }

    const uint32_t s_lo = (uint32_t)(r_lo * SMS + q_lo * 16);
    const uint32_t s_hi = (uint32_t)(r_hi * SMS + q_hi * 16);

    const int nch = K >> 5;

    {
        #pragma unroll
        for (int s = 0; s < 4; ++s) {
            cp16(sbase + s * MATB + s_lo, srcs[s] + (size_t)r_lo * K + q_lo * 8);
            cp16(sbase + s * MATB + s_hi, srcs[s] + (size_t)r_hi * K + q_hi * 8);
        }
        CP_COMMIT();
    }
    CP_WAIT0();
    __syncthreads();

    for (int c = 0; c < nch; ++c) {
        if (c + 1 < nch) {
            const int k0 = (c + 1) << 5;
            const uint32_t sb = sbase + ((c + 1) & 1) * STAGEB;
            #pragma unroll
            for (int s = 0; s < 4; ++s) {
                cp16(sb + s * MATB + s_lo, srcs[s] + (size_t)r_lo * K + k0 + q_lo * 8);
                cp16(sb + s * MATB + s_hi, srcs[s] + (size_t)r_hi * K + k0 + q_hi * 8);
            }
        }
        CP_COMMIT();

        const uint32_t stoff = (uint32_t)((c & 1) * STAGEB);
        #pragma unroll
        for (int ks = 0; ks < 2; ++ks) {
            uint32_t ah[4][4], al[4][4];
            #pragma unroll
            for (int mf = 0; mf < 4; ++mf) {
                ldsm_x4(ah[mf], aAddrH[mf] + stoff + ks * 32);
                ldsm_x4(al[mf], aAddrL[mf] + stoff + ks * 32);
            }
            #pragma unroll
            for (int np = 0; np < 2; ++np) {
                uint32_t bh[4], bl[4];
                ldsm_x4(bh, bAddrH[np] + stoff + ks * 32);
                ldsm_x4(bl, bAddrL[np] + stoff + ks * 32);
                #pragma unroll
                for (int half = 0; half < 2; ++half) {
                    const int nf = np * 2 + half;
                    const uint32_t bh0 = bh[half], bh1 = bh[half + 2];
                    const uint32_t bl0 = bl[half], bl1 = bl[half + 2];
                    #pragma unroll
                    for (int mf = 0; mf < 4; ++mf) {
                        mma_bf16(acc[mf][nf], ah[mf], bh0, bh1);
                        mma_bf16(acc[mf][nf], ah[mf], bl0, bl1);
                        mma_bf16(acc[mf][nf], al[mf], bh0, bh1);
                    }
                }
            }
        }

        CP_WAIT0();
        __syncthreads();
    }

    const int trow = lane >> 2;
    const int tcol = (lane & 3) * 2;
    #pragma unroll
    for (int mf = 0; mf < 4; ++mf) {
        #pragma unroll
        for (int nf = 0; nf < 4; ++nf) {
            const int r   = m0 + warp_m * 64 + mf * 16 + trow;
            const int col = n0 + warp_n * 32 + nf * 8 + tcol;
            const float b0 = bias[col], b1 = bias[col + 1];
            float2 v0, v1;
            v0.x = acc[mf][nf][0] + b0; v0.y = acc[mf][nf][1] + b1;
            v1.x = acc[mf][nf][2] + b0; v1.y = acc[mf][nf][3] + b1;
            *(float2*)&C[(size_t)r * N + col]       = v0;
            *(float2*)&C[(size_t)(r + 8) * N + col] = v1;
        }
    }
}

// ---------------- RMSNorm + RoPE, in place on q and k heads -----------------
__global__ __launch_bounds__(128) void norm_rope_kernel(
    const float* __restrict__ pe,
    const float* __restrict__ q_scale,
    const float* __restrict__ k_scale)
{
    const int t  = blockIdx.x;
    const int hh = blockIdx.y;
    const bool isK = hh >= N_HEADS;
    const int h  = hh & (N_HEADS - 1);
    const int d  = threadIdx.x;

    float* base = g_qkv + (size_t)t * QKV_COLS + (isK ? D_MODEL : 0) + h * D_HEAD;

    float v = base[d];
    float sq = v * v;
    #pragma unroll
    for (int o = 16; o > 0; o >>= 1)
        sq += __shfl_xor_sync(0xffffffffu, sq, o);

    __shared__ float red[4];
    __shared__ float sn[D_HEAD];
    const int wid = d >> 5;
    if ((d & 31) == 0) red[wid] = sq;
    __syncthreads();
    const float tot = red[0] + red[1] + red[2] + red[3];
    const float rrms = rsqrtf(tot * (1.f / D_HEAD) + EPS);

    const float* sc = isK ? k_scale : q_scale;
    sn[d] = v * rrms * sc[d];
    __syncthreads();

    const float c = pe[(size_t)t * 256 + (d & ~1)];
    const float s = pe[(size_t)t * 256 + 128 + (d & ~1)];
    const float v0 = sn[d & ~1];
    const float v1 = sn[d | 1];
    base[d] = (d & 1) ? (v0 * s + v1 * c) : (v0 * c - v1 * s);
}

// ================= HMMA flash attention (split-bf16 3-pass) =================
// Block: 256 thr = 8 warps, grid (32 q-tiles, 16 heads). BQ=64, BKEY=64.
// S GEMM: warps 4m x 2n (tile 16x32); PV GEMM: warps 4m x 2n (tile 16x64).
// Q/K smem row stride 272B; V^T / P stride 144B (both 16B-phase conflict-free).
#define AQ_STRIDE 136   // bf16 units (272 B)
#define AV_STRIDE 72    // bf16 units (144 B)
#define AS_STRIDE 72    // fp32 units (288 B)

struct AttnSmem {
    __nv_bfloat16 Qh[64 * AQ_STRIDE];
    __nv_bfloat16 Ql[64 * AQ_STRIDE];
    union {
        struct { __nv_bfloat16 h[64 * AQ_STRIDE], l[64 * AQ_STRIDE]; } K;
        struct { __nv_bfloat16 h[128 * AV_STRIDE], l[128 * AV_STRIDE]; } V;  // V^T [d][j]
        float Sf[64 * AS_STRIDE];
    } A;
    __nv_bfloat16 Ph[64 * AV_STRIDE];
    __nv_bfloat16 Pl[64 * AV_STRIDE];
    float m[64], l[64], newm[64], cf[64];
};

__global__ __launch_bounds__(256, 2) void attn_mma_kernel(const int* __restrict__ seq_lens)
{
    extern __shared__ __align__(16) char smem_raw[];
    AttnSmem& S = *reinterpret_cast<AttnSmem*>(smem_raw);

    const int tid = threadIdx.x;
    const int lane = tid & 31, wid = tid >> 5;
    const int wm = wid >> 1, wn = wid & 1;
    const int h  = blockIdx.y;
    const int q0 = blockIdx.x * 64;

    int start = 0, len = 0;
    #pragma unroll
    for (int i = 0; i < 4; ++i) {
        len = seq_lens[i];
        if (q0 < start + len) break;
        start += len;
    }
    const int end = start + len;

    // ---- load Q tile, split hi/lo ----
    #pragma unroll 4
    for (int it = 0; it < 32; ++it) {
        const int e = tid + it * 256;
        const int d = e & 127, r = e >> 7;
        const float v = g_qkv[(size_t)(q0 + r) * QKV_COLS + h * D_HEAD + d];
        const __nv_bfloat16 hv = __float2bfloat16(v);
        S.Qh[r * AQ_STRIDE + d] = hv;
        S.Ql[r * AQ_STRIDE + d] = __float2bfloat16(v - __bfloat162float(hv));
    }
    if (tid < 64) { S.m[tid] = -INFINITY; S.l[tid] = 0.f; }

    float o[8][4];
    #pragma unroll
    for (int nf = 0; nf < 8; ++nf)
        #pragma unroll
        for (int k = 0; k < 4; ++k) o[nf][k] = 0.f;

    const int lrow = lane & 15, lcol = (lane >> 4) * 16;
    const uint32_t aQh = smem_to_u32(S.Qh)    + (wm * 16 + lrow) * 272 + lcol;
    const uint32_t aQl = smem_to_u32(S.Ql)    + (wm * 16 + lrow) * 272 + lcol;
    const uint32_t aK0h = smem_to_u32(S.A.K.h) + (wn * 32 + lrow) * 272 + lcol;
    const uint32_t aK0l = smem_to_u32(S.A.K.l) + (wn * 32 + lrow) * 272 + lcol;
    const uint32_t aPh = smem_to_u32(S.Ph)    + (wm * 16 + lrow) * 144 + lcol;
    const uint32_t aPl = smem_to_u32(S.Pl)    + (wm * 16 + lrow) * 144 + lcol;
    const uint32_t aVhB = smem_to_u32(S.A.V.h) + (wn * 64 + lrow) * 144 + lcol;
    const uint32_t aVlB = smem_to_u32(S.A.V.l) + (wn * 64 + lrow) * 144 + lcol;

    const int crow  = wm * 16 + (lane >> 2);     // C-frag row (first half)
    const int ccol0 = (lane & 3) * 2;

    const int ty = tid >> 4, tx = tid & 15;
    const int r0 = ty * 4, c0 = tx * 4;

    for (int j0 = start; j0 < end; j0 += 64) {
        __syncthreads();   // BufA + P free (prev PV / softmax reads done)

        // ---- load K tile, split hi/lo ----
        #pragma unroll 4
        for (int it = 0; it < 32; ++it) {
            const int e = tid + it * 256;
            const int d = e & 127, r = e >> 7;
            const float v = g_qkv[(size_t)(j0 + r) * QKV_COLS + D_MODEL + h * D_HEAD + d];
            const __nv_bfloat16 hv = __float2bfloat16(v);
            S.A.K.h[r * AQ_STRIDE + d] = hv;
            S.A.K.l[r * AQ_STRIDE + d] = __float2bfloat16(v - __bfloat162float(hv));
        }
        __syncthreads();

        // ---- S = Q K^T (3-pass HMMA), warp tile 16x32 ----
        float sacc[4][4];
        #pragma unroll
        for (int nf = 0; nf < 4; ++nf)
            #pragma unroll
            for (int k = 0; k < 4; ++k) sacc[nf][k] = 0.f;

        #pragma unroll
        for (int ks = 0; ks < 8; ++ks) {
            const uint32_t off = ks * 32;
            uint32_t ah[4], al[4], bh[2][4], bl[2][4];
            ldsm_x4(ah, aQh + off);
            ldsm_x4(al, aQl + off);
            ldsm_x4(bh[0], aK0h + off);
            ldsm_x4(bh[1], aK0h + 16 * 272 + off);
            ldsm_x4(bl[0], aK0l + off);
            ldsm_x4(bl[1], aK0l + 16 * 272 + off);
            #pragma unroll
            for (int nb = 0; nb < 2; ++nb) {
                #pragma unroll
                for (int half = 0; half < 2; ++half) {
                    const int nf = nb * 2 + half;
                    mma_bf16(sacc[nf], ah, bh[nb][half], bh[nb][half + 2]);
                    mma_bf16(sacc[nf], ah, bl[nb][half], bl[nb][half + 2]);
                    mma_bf16(sacc[nf], al, bh[nb][half], bh[nb][half + 2]);
                }
            }
        }
        __syncthreads();   // all warps done reading K; BufA reusable as Sf

        // ---- store scaled S to smem ----
        #pragma unroll
        for (int nf = 0; nf < 4; ++nf) {
            const int col = wn * 32 + nf * 8 + ccol0;
            float2 v0, v1;
            v0.x = sacc[nf][0] * SM_SCALE; v0.y = sacc[nf][1] * SM_SCALE;
            v1.x = sacc[nf][2] * SM_SCALE; v1.y = sacc[nf][3] * SM_SCALE;
            *(float2*)&S.A.Sf[crow * AS_STRIDE + col]       = v0;
            *(float2*)&S.A.Sf[(crow + 8) * AS_STRIDE + col] = v1;
        }
        __syncthreads();

        // ---- online softmax (16-thread row groups, as before) ----
        float s4[4][4];
        #pragma unroll
        for (int i = 0; i < 4; ++i) {
            const float4 sv = *(const float4*)&S.A.Sf[(r0 + i) * AS_STRIDE + c0];
            s4[i][0] = sv.x; s4[i][1] = sv.y; s4[i][2] = sv.z; s4[i][3] = sv.w;
        }
        float rmax[4];
        #pragma unroll
        for (int i = 0; i < 4; ++i) {
            float v = fmaxf(fmaxf(s4[i][0], s4[i][1]), fmaxf(s4[i][2], s4[i][3]));
            #pragma unroll
            for (int off = 8; off > 0; off >>= 1)
                v = fmaxf(v, __shfl_xor_sync(0xffffffffu, v, off));
            rmax[i] = v;
        }
        if (tx == 0) {
            #pragma unroll
            for (int i = 0; i < 4; ++i) {
                const float mo = S.m[r0 + i];
                const float mn = fmaxf(mo, rmax[i]);
                S.newm[r0 + i] = mn;
                S.cf[r0 + i]   = __expf(mo - mn);
                S.m[r0 + i]    = mn;
            }
        }
        __syncthreads();

        float rs[4];
        #pragma unroll
        for (int i = 0; i < 4; ++i) {
            const float mn = S.newm[r0 + i];
            #pragma unroll
            for (int j = 0; j < 4; ++j) s4[i][j] = __expf(s4[i][j] - mn);
            rs[i] = (s4[i][0] + s4[i][1]) + (s4[i][2] + s4[i][3]);
            #pragma unroll
            for (int off = 8; off > 0; off >>= 1)
                rs[i] += __shfl_xor_sync(0xffffffffu, rs[i], off);
        }
        if (tx == 0) {
            #pragma unroll
            for (int i = 0; i < 4; ++i)
                S.l[r0 + i] = S.l[r0 + i] * S.cf[r0 + i] + rs[i];
        }
        // write P hi/lo (4 bf16 = two bf162 per row)
        #pragma unroll
        for (int i = 0; i < 4; ++i) {
            __nv_bfloat16 h0 = __float2bfloat16(s4[i][0]);
            __nv_bfloat16 h1 = __float2bfloat16(s4[i][1]);
            __nv_bfloat16 h2 = __float2bfloat16(s4[i][2]);
            __nv_bfloat16 h3 = __float2bfloat16(s4[i][3]);
            __nv_bfloat162 hp0; hp0.x = h0; hp0.y = h1;
            __nv_bfloat162 hp1; hp1.x = h2; hp1.y = h3;
            __nv_bfloat162 lp0, lp1;
            lp0.x = __float2bfloat16(s4[i][0] - __bfloat162float(h0));
            lp0.y = __float2bfloat16(s4[i][1] - __bfloat162float(h1));
            lp1.x = __float2bfloat16(s4[i][2] - __bfloat162float(h2));
            lp1.y = __float2bfloat16(s4[i][3] - __bfloat162float(h3));
            *(__nv_bfloat162*)&S.Ph[(r0 + i) * AV_STRIDE + c0]     = hp0;
            *(__nv_bfloat162*)&S.Ph[(r0 + i) * AV_STRIDE + c0 + 2] = hp1;
            *(__nv_bfloat162*)&S.Pl[(r0 + i) * AV_STRIDE + c0]     = lp0;
            *(__nv_bfloat162*)&S.Pl[(r0 + i) * AV_STRIDE + c0 + 2] = lp1;
        }
        __syncthreads();   // Sf reads done; stats/P visible; BufA -> V

        // ---- load V tile transposed (V^T[d][j]), split hi/lo ----
        #pragma unroll 4
        for (int it = 0; it < 32; ++it) {
            const int e = tid + it * 256;
            const int d = e & 127, j = e >> 7;
            const float v = g_qkv[(size_t)(j0 + j) * QKV_COLS + 2 * D_MODEL + h * D_HEAD + d];
            const __nv_bfloat16 hv = __float2bfloat16(v);
            S.A.V.h[d * AV_STRIDE + j] = hv;
            S.A.V.l[d * AV_STRIDE + j] = __float2bfloat16(v - __bfloat162float(hv));
        }
        // rescale O by cf (stats visible since softmax barrier)
        {
            const float cf1 = S.cf[crow];
            const float cf2 = S.cf[crow + 8];
            #pragma unroll
            for (int nf = 0; nf < 8; ++nf) {
                o[nf][0] *= cf1; o[nf][1] *= cf1;
                o[nf][2] *= cf2; o[nf][3] *= cf2;
            }
        }
        __syncthreads();

        // ---- O += P V (3-pass HMMA), warp tile 16x64 ----
        #pragma unroll
        for (int ks = 0; ks < 4; ++ks) {
            const uint32_t off = ks * 32;
            uint32_t pah[4], pal[4];
            ldsm_x4(pah, aPh + off);
            ldsm_x4(pal, aPl + off);
            #pragma unroll
            for (int nb = 0; nb < 4; ++nb) {
                uint32_t vh[4], vl[4];
                ldsm_x4(vh, aVhB + nb * 16 * 144 + off);
                ldsm_x4(vl, aVlB + nb * 16 * 144 + off);
                #pragma unroll
                for (int half = 0; half < 2; ++half) {
                    const int nf = nb * 2 + half;
                    mma_bf16(o[nf], pah, vh[half], vh[half + 2]);
                    mma_bf16(o[nf], pah, vl[half], vl[half + 2]);
                    mma_bf16(o[nf], pal, vh[half], vh[half + 2]);
                }
            }
        }
    }

    // ---- epilogue: normalize, split hi/lo, store to g_ahi/g_alo ----
    const float linv1 = 1.f / S.l[crow];
    const float linv2 = 1.f / S.l[crow + 8];
    const int gr1 = q0 + crow, gr2 = q0 + crow + 8;
    #pragma unroll
    for (int nf = 0; nf < 8; ++nf) {
        const int col = h * D_HEAD + wn * 64 + nf * 8 + ccol0;
        float v0 = o[nf][0] * linv1, v1 = o[nf][1] * linv1;
        float v2 = o[nf][2] * linv2, v3 = o[nf][3] * linv2;
        __nv_bfloat16 h0 = __float2bfloat16(v0), h1 = __float2bfloat16(v1);
        __nv_bfloat16 h2 = __float2bfloat16(v2), h3 = __float2bfloat16(v3);
        __nv_bfloat162 hp0; hp0.x = h0; hp0.y = h1;
        __nv_bfloat162 hp1; hp1.x = h2; hp1.y = h3;
        __nv_bfloat162 lp0, lp1;
        lp0.x = __float2bfloat16(v0 - __bfloat162float(h0));
        lp0.y = __float2bfloat16(v1 - __bfloat162float(h1));
        lp1.x = __float2bfloat16(v2 - __bfloat162float(h2));
        lp1.y = __float2bfloat16(v3 - __bfloat162float(h3));
        *(__nv_bfloat162*)&g_ahi[(size_t)gr1 * D_MODEL + col] = hp0;
        *(__nv_bfloat162*)&g_alo[(size_t)gr1 * D_MODEL + col] = lp0;
        *(__nv_bfloat162*)&g_ahi[(size_t)gr2 * D_MODEL + col] = hp1;
        *(__nv_bfloat162*)&g_alo[(size_t)gr2 * D_MODEL + col] = lp1;
    }
}

// ---------------------------------------------------------------------------
extern "C" void kernel_launch(void* const* d_in, const int* in_sizes, int n_in,
                              void* d_out, int out_size)
{
    const float* x        = (const float*)d_in[0];
    const float* pe       = (const float*)d_in[1];
    const int*   seq_lens = (const int*)  d_in[2];
    const float* qkv_w    = (const float*)d_in[3];
    const float* qkv_b    = (const float*)d_in[4];
    const float* q_scale  = (const float*)d_in[5];
    const float* k_scale  = (const float*)d_in[6];
    const float* proj_w   = (const float*)d_in[7];
    const float* proj_b   = (const float*)d_in[8];
    float* out = (float*)d_out;

    float *qkv_ptr = nullptr;
    __nv_bfloat16 *xhi, *xlo, *wqh, *wql, *wph, *wpl, *ahi, *alo;
    cudaGetSymbolAddress((void**)&qkv_ptr,  g_qkv);
    cudaGetSymbolAddress((void**)&xhi, g_xhi);
    cudaGetSymbolAddress((void**)&xlo, g_xlo);
    cudaGetSymbolAddress((void**)&wqh, g_wqkv_hi);
    cudaGetSymbolAddress((void**)&wql, g_wqkv_lo);
    cudaGetSymbolAddress((void**)&wph, g_wp_hi);
    cudaGetSymbolAddress((void**)&wpl, g_wp_lo);
    cudaGetSymbolAddress((void**)&ahi, g_ahi);
    cudaGetSymbolAddress((void**)&alo, g_alo);

    const int attn_smem = (int)sizeof(AttnSmem);
    cudaFuncSetAttribute(attn_mma_kernel,
                         cudaFuncAttributeMaxDynamicSharedMemorySize, attn_smem);
    cudaFuncSetAttribute(gemm_mma,
                         cudaFuncAttributeMaxDynamicSharedMemorySize, GEMM_SMEM);

    // 0) split inputs into bf16 hi/lo
    {
        const int n4x = (L_TOTAL * D_MODEL) / 4;      // 1M
        const int n4w = (QKV_COLS * D_MODEL) / 4;     // 3M
        split_bf16_kernel<<<n4x / 256, 256>>>(x, xhi, xlo, n4x);
        split_bf16_kernel<<<n4w / 256, 256>>>(qkv_w, wqh, wql, n4w);
        split_bf16_kernel<<<n4x / 256, 256>>>(proj_w, wph, wpl, n4x);
    }

    // 1) qkv = x @ qkv_w^T + qkv_b   (HMMA, split-bf16 3-pass, 2-stage async)
    gemm_mma<<<dim3(QKV_COLS / 128, L_TOTAL / 128), 256, GEMM_SMEM>>>(
        xhi, xlo, wqh, wql, qkv_b, qkv_ptr, QKV_COLS, D_MODEL);

    // 2) RMSNorm + RoPE in place on q, k
    norm_rope_kernel<<<dim3(L_TOTAL, 2 * N_HEADS), 128>>>(pe, q_scale, k_scale);

    // 3) block-diagonal flash attention (HMMA) -> g_ahi/g_alo directly
    attn_mma_kernel<<<dim3(L_TOTAL / 64, N_HEADS), 256, attn_smem>>>(seq_lens);

    // 4) out = attn @ proj_w^T + proj_b
    gemm_mma<<<dim3(D_MODEL / 128, L_TOTAL / 128), 256, GEMM_SMEM>>>(
        ahi, alo, wph, wpl, proj_b, out, D_MODEL, D_MODEL);
}

// round 16
// speedup vs baseline: 1.5613x; 1.5613x over previous
#include <cuda_runtime.h>
#include <cuda_bf16.h>
#include <math.h>
#include <cstdint>

#define L_TOTAL 2048
#define D_MODEL 2048
#define D_HEAD  128
#define N_HEADS 16
#define QKV_COLS (3 * D_MODEL)   // 6144
#define EPS 1e-6f
#define SM_SCALE 0.08838834764831845f   // 1/sqrt(128)

// ---------------- scratch (device globals: allocation-free rule) ------------
__device__ float g_qkv[(size_t)L_TOTAL * QKV_COLS];   // [L, 6144] = q|k|v (fp32)

__device__ __nv_bfloat16 g_xhi[(size_t)L_TOTAL * D_MODEL];
__device__ __nv_bfloat16 g_xlo[(size_t)L_TOTAL * D_MODEL];
__device__ __nv_bfloat16 g_wqkv_hi[(size_t)QKV_COLS * D_MODEL];
__device__ __nv_bfloat16 g_wqkv_lo[(size_t)QKV_COLS * D_MODEL];
__device__ __nv_bfloat16 g_wp_hi[(size_t)D_MODEL * D_MODEL];
__device__ __nv_bfloat16 g_wp_lo[(size_t)D_MODEL * D_MODEL];
__device__ __nv_bfloat16 g_ahi[(size_t)L_TOTAL * D_MODEL];
__device__ __nv_bfloat16 g_alo[(size_t)L_TOTAL * D_MODEL];

// normed+roped q,k in split bf16, row-major [t][h*128+d]
__device__ __nv_bfloat16 g_qh[(size_t)L_TOTAL * D_MODEL];
__device__ __nv_bfloat16 g_ql[(size_t)L_TOTAL * D_MODEL];
__device__ __nv_bfloat16 g_kh[(size_t)L_TOTAL * D_MODEL];
__device__ __nv_bfloat16 g_kl[(size_t)L_TOTAL * D_MODEL];

// =================== helpers ================================================
__device__ __forceinline__ uint32_t smem_to_u32(const void* p) {
    uint32_t a;
    asm("{ .reg .u64 t; cvta.to.shared.u64 t, %1; cvt.u32.u64 %0, t; }"
        : "=r"(a) : "l"(p));
    return a;
}

__device__ __forceinline__ void ldsm_x4(uint32_t* r, uint32_t addr) {
    asm volatile("ldmatrix.sync.aligned.m8n8.x4.shared.b16 {%0,%1,%2,%3}, [%4];"
                 : "=r"(r[0]), "=r"(r[1]), "=r"(r[2]), "=r"(r[3]) : "r"(addr));
}

__device__ __forceinline__ void mma_bf16(float* c, const uint32_t* a,
                                         uint32_t b0, uint32_t b1) {
    asm volatile(
        "mma.sync.aligned.m16n8k16.row.col.f32.bf16.bf16.f32 "
        "{%0,%1,%2,%3}, {%4,%5,%6,%7}, {%8,%9}, {%0,%1,%2,%3};\n"
        : "+f"(c[0]), "+f"(c[1]), "+f"(c[2]), "+f"(c[3])
        : "r"(a[0]), "r"(a[1]), "r"(a[2]), "r"(a[3]), "r"(b0), "r"(b1));
}

__device__ __forceinline__ void cp16(uint32_t saddr, const void* gaddr) {
    asm volatile("cp.async.cg.shared.global [%0], [%1], 16;"
                 :: "r"(saddr), "l"(gaddr));
}
#define CP_COMMIT() asm volatile("cp.async.commit_group;" ::: "memory")
#define CP_WAIT0()  asm volatile("cp.async.wait_group 0;" ::: "memory")

// =================== split fp32 -> bf16 hi + bf16 lo ========================
__global__ __launch_bounds__(256) void split_bf16_kernel(
    const float* __restrict__ src,
    __nv_bfloat16* __restrict__ hi, __nv_bfloat16* __restrict__ lo, int n4)
{
    const int i = blockIdx.x * 256 + threadIdx.x;
    if (i >= n4) return;
    const float4 v = ((const float4*)src)[i];
    __nv_bfloat16 h0 = __float2bfloat16(v.x);
    __nv_bfloat16 h1 = __float2bfloat16(v.y);
    __nv_bfloat16 h2 = __float2bfloat16(v.z);
    __nv_bfloat16 h3 = __float2bfloat16(v.w);
    __nv_bfloat16 l0 = __float2bfloat16(v.x - __bfloat162float(h0));
    __nv_bfloat16 l1 = __float2bfloat16(v.y - __bfloat162float(h1));
    __nv_bfloat16 l2 = __float2bfloat16(v.z - __bfloat162float(h2));
    __nv_bfloat16 l3 = __float2bfloat16(v.w - __bfloat162float(h3));
    __nv_bfloat162 hp0; hp0.x = h0; hp0.y = h1;
    __nv_bfloat162 hp1; hp1.x = h2; hp1.y = h3;
    __nv_bfloat162 lp0; lp0.x = l0; lp0.y = l1;
    __nv_bfloat162 lp1; lp1.x = l2; lp1.y = l3;
    ((__nv_bfloat162*)hi)[2 * i]     = hp0;
    ((__nv_bfloat162*)hi)[2 * i + 1] = hp1;
    ((__nv_bfloat162*)lo)[2 * i]     = lp0;
    ((__nv_bfloat162*)lo)[2 * i + 1] = lp1;
}

// =================== HMMA split-bf16 GEMM (cp.async 2-stage, 2 CTA/SM) ======
#define SMS 80
#define MATB (128 * SMS)
#define STAGEB (4 * MATB)
#define NSTAGE 2
#define GEMM_SMEM (NSTAGE * STAGEB)  // 81920 B

__global__ __launch_bounds__(256, 2) void gemm_mma(
    const __nv_bfloat16* __restrict__ Ahi, const __nv_bfloat16* __restrict__ Alo,
    const __nv_bfloat16* __restrict__ Bhi, const __nv_bfloat16* __restrict__ Blo,
    const float* __restrict__ bias, float* __restrict__ C, int N, int K)
{
    extern __shared__ __align__(16) char sm[];

    const int tid = threadIdx.x;
    const int lane = tid & 31, wid = tid >> 5;
    const int warp_m = wid >> 2, warp_n = wid & 3;
    const int m0 = blockIdx.y * 128, n0 = blockIdx.x * 128;

    const __nv_bfloat16* srcs[4];
    srcs[0] = Ahi + (size_t)m0 * K;
    srcs[1] = Alo + (size_t)m0 * K;
    srcs[2] = Bhi + (size_t)n0 * K;
    srcs[3] = Blo + (size_t)n0 * K;

    const int r_lo = tid >> 2,          q_lo = tid & 3;
    const int r_hi = (tid + 256) >> 2,  q_hi = tid & 3;

    const uint32_t sbase = smem_to_u32(sm);

    float acc[4][4][4];
    #pragma unroll
    for (int a = 0; a < 4; ++a)
        #pragma unroll
        for (int b = 0; b < 4; ++b)
            #pragma unroll
            for (int cc = 0; cc < 4; ++cc) acc[a][b][cc] = 0.f;

    const int lrow = lane & 15;
    const int lcol = (lane >> 4) * 16;
    uint32_t aAddrH[4], aAddrL[4], bAddrH[2], bAddrL[2];
    #pragma unroll
    for (int mf = 0; mf < 4; ++mf) {
        const int r = warp_m * 64 + mf * 16 + lrow;
        aAddrH[mf] = sbase + 0 * MATB + r * SMS + lcol;
        aAddrL[mf] = sbase + 1 * MATB + r * SMS + lcol;
    }
    #pragma unroll
    for (int np = 0; np < 2; ++np) {
        const int r = warp_n * 32 + np * 16 + lrow;
        bAddrH[np] = sbase + 2 * MATB + r * SMS + lcol;
        bAddrL[np] = sbase + 3 * MATB + r * SMS + lcol;
    }

    const uint32_t s_lo = (uint32_t)(r_lo * SMS + q_lo * 16);
    const uint32_t s_hi = (uint32_t)(r_hi * SMS + q_hi * 16);

    const int nch = K >> 5;

    {
        #pragma unroll
        for (int s = 0; s < 4; ++s) {
            cp16(sbase + s * MATB + s_lo, srcs[s] + (size_t)r_lo * K + q_lo * 8);
            cp16(sbase + s * MATB + s_hi, srcs[s] + (size_t)r_hi * K + q_hi * 8);
        }
        CP_COMMIT();
    }
    CP_WAIT0();
    __syncthreads();

    for (int c = 0; c < nch; ++c) {
        if (c + 1 < nch) {
            const int k0 = (c + 1) << 5;
            const uint32_t sb = sbase + ((c + 1) & 1) * STAGEB;
            #pragma unroll
            for (int s = 0; s < 4; ++s) {
                cp16(sb + s * MATB + s_lo, srcs[s] + (size_t)r_lo * K + k0 + q_lo * 8);
                cp16(sb + s * MATB + s_hi, srcs[s] + (size_t)r_hi * K + k0 + q_hi * 8);
            }
        }
        CP_COMMIT();

        const uint32_t stoff = (uint32_t)((c & 1) * STAGEB);
        #pragma unroll
        for (int ks = 0; ks < 2; ++ks) {
            uint32_t ah[4][4], al[4][4];
            #pragma unroll
            for (int mf = 0; mf < 4; ++mf) {
                ldsm_x4(ah[mf], aAddrH[mf] + stoff + ks * 32);
                ldsm_x4(al[mf], aAddrL[mf] + stoff + ks * 32);
            }
            #pragma unroll
            for (int np = 0; np < 2; ++np) {
                uint32_t bh[4], bl[4];
                ldsm_x4(bh, bAddrH[np] + stoff + ks * 32);
                ldsm_x4(bl, bAddrL[np] + stoff + ks * 32);
                #pragma unroll
                for (int half = 0; half < 2; ++half) {
                    const int nf = np * 2 + half;
                    const uint32_t bh0 = bh[half], bh1 = bh[half + 2];
                    const uint32_t bl0 = bl[half], bl1 = bl[half + 2];
                    #pragma unroll
                    for (int mf = 0; mf < 4; ++mf) {
                        mma_bf16(acc[mf][nf], ah[mf], bh0, bh1);
                        mma_bf16(acc[mf][nf], ah[mf], bl0, bl1);
                        mma_bf16(acc[mf][nf], al[mf], bh0, bh1);
                    }
                }
            }
        }

        CP_WAIT0();
        __syncthreads();
    }

    const int trow = lane >> 2;
    const int tcol = (lane & 3) * 2;
    #pragma unroll
    for (int mf = 0; mf < 4; ++mf) {
        #pragma unroll
        for (int nf = 0; nf < 4; ++nf) {
            const int r   = m0 + warp_m * 64 + mf * 16 + trow;
            const int col = n0 + warp_n * 32 + nf * 8 + tcol;
            const float b0 = bias[col], b1 = bias[col + 1];
            float2 v0, v1;
            v0.x = acc[mf][nf][0] + b0; v0.y = acc[mf][nf][1] + b1;
            v1.x = acc[mf][nf][2] + b0; v1.y = acc[mf][nf][3] + b1;
            *(float2*)&C[(size_t)r * N + col]       = v0;
            *(float2*)&C[(size_t)(r + 8) * N + col] = v1;
        }
    }
}

// ---------------- RMSNorm + RoPE: q,k -> split bf16 globals -----------------
__global__ __launch_bounds__(128) void norm_rope_kernel(
    const float* __restrict__ pe,
    const float* __restrict__ q_scale,
    const float* __restrict__ k_scale)
{
    const int t  = blockIdx.x;
    const int hh = blockIdx.y;
    const bool isK = hh >= N_HEADS;
    const int h  = hh & (N_HEADS - 1);
    const int d  = threadIdx.x;

    const float* base = g_qkv + (size_t)t * QKV_COLS + (isK ? D_MODEL : 0) + h * D_HEAD;

    float v = base[d];
    float sq = v * v;
    #pragma unroll
    for (int o = 16; o > 0; o >>= 1)
        sq += __shfl_xor_sync(0xffffffffu, sq, o);

    __shared__ float red[4];
    __shared__ float sn[D_HEAD];
    const int wid = d >> 5;
    if ((d & 31) == 0) red[wid] = sq;
    __syncthreads();
    const float tot = red[0] + red[1] + red[2] + red[3];
    const float rrms = rsqrtf(tot * (1.f / D_HEAD) + EPS);

    const float* sc = isK ? k_scale : q_scale;
    sn[d] = v * rrms * sc[d];
    __syncthreads();

    const float c = pe[(size_t)t * 256 + (d & ~1)];
    const float s = pe[(size_t)t * 256 + 128 + (d & ~1)];
    const float v0 = sn[d & ~1];
    const float v1 = sn[d | 1];
    const float r = (d & 1) ? (v0 * s + v1 * c) : (v0 * c - v1 * s);

    const __nv_bfloat16 hv = __float2bfloat16(r);
    const __nv_bfloat16 lv = __float2bfloat16(r - __bfloat162float(hv));
    const size_t idx = (size_t)t * D_MODEL + h * D_HEAD + d;
    if (isK) { g_kh[idx] = hv; g_kl[idx] = lv; }
    else     { g_qh[idx] = hv; g_ql[idx] = lv; }
}

// ================= HMMA flash attention (split-bf16 3-pass) =================
// Q/K tiles now arrive pre-split in bf16 via cp.async; V converted in-kernel.
#define AQ_STRIDE 136   // bf16 units (272 B)
#define AV_STRIDE 72    // bf16 units (144 B)
#define AS_STRIDE 72    // fp32 units (288 B)

struct AttnSmem {
    __nv_bfloat16 Qh[64 * AQ_STRIDE];
    __nv_bfloat16 Ql[64 * AQ_STRIDE];
    union {
        struct { __nv_bfloat16 h[64 * AQ_STRIDE], l[64 * AQ_STRIDE]; } K;
        struct { __nv_bfloat16 h[128 * AV_STRIDE], l[128 * AV_STRIDE]; } V;  // V^T [d][j]
        float Sf[64 * AS_STRIDE];
    } A;
    __nv_bfloat16 Ph[64 * AV_STRIDE];
    __nv_bfloat16 Pl[64 * AV_STRIDE];
    float m[64], l[64], newm[64], cf[64];
};

__global__ __launch_bounds__(256, 2) void attn_mma_kernel(const int* __restrict__ seq_lens)
{
    extern __shared__ __align__(16) char smem_raw[];
    AttnSmem& S = *reinterpret_cast<AttnSmem*>(smem_raw);

    const int tid = threadIdx.x;
    const int lane = tid & 31, wid = tid >> 5;
    const int wm = wid >> 1, wn = wid & 1;
    const int h  = blockIdx.y;
    const int q0 = blockIdx.x * 64;

    int start = 0, len = 0;
    #pragma unroll
    for (int i = 0; i < 4; ++i) {
        len = seq_lens[i];
        if (q0 < start + len) break;
        start += len;
    }
    const int end = start + len;

    const uint32_t sQh = smem_to_u32(S.Qh);
    const uint32_t sQl = smem_to_u32(S.Ql);
    const uint32_t sKh = smem_to_u32(S.A.K.h);
    const uint32_t sKl = smem_to_u32(S.A.K.l);

    // ---- load Q tile via cp.async (pre-split bf16) ----
    #pragma unroll
    for (int it = 0; it < 4; ++it) {
        const int e = tid + it * 256;          // 1024 chunks of 16B
        const int r = e >> 4, c = e & 15;
        const size_t gsrc = (size_t)(q0 + r) * D_MODEL + h * D_HEAD + c * 8;
        cp16(sQh + r * 272 + c * 16, &g_qh[gsrc]);
        cp16(sQl + r * 272 + c * 16, &g_ql[gsrc]);
    }
    CP_COMMIT();
    if (tid < 64) { S.m[tid] = -INFINITY; S.l[tid] = 0.f; }

    float o[8][4];
    #pragma unroll
    for (int nf = 0; nf < 8; ++nf)
        #pragma unroll
        for (int k = 0; k < 4; ++k) o[nf][k] = 0.f;

    const int lrow = lane & 15, lcol = (lane >> 4) * 16;
    const uint32_t aQh = sQh + (wm * 16 + lrow) * 272 + lcol;
    const uint32_t aQl = sQl + (wm * 16 + lrow) * 272 + lcol;
    const uint32_t aK0h = sKh + (wn * 32 + lrow) * 272 + lcol;
    const uint32_t aK0l = sKl + (wn * 32 + lrow) * 272 + lcol;
    const uint32_t aPh = smem_to_u32(S.Ph)    + (wm * 16 + lrow) * 144 + lcol;
    const uint32_t aPl = smem_to_u32(S.Pl)    + (wm * 16 + lrow) * 144 + lcol;
    const uint32_t aVhB = smem_to_u32(S.A.V.h) + (wn * 64 + lrow) * 144 + lcol;
    const uint32_t aVlB = smem_to_u32(S.A.V.l) + (wn * 64 + lrow) * 144 + lcol;

    const int crow  = wm * 16 + (lane >> 2);
    const int ccol0 = (lane & 3) * 2;

    const int ty = tid >> 4, tx = tid & 15;
    const int r0 = ty * 4, c0 = tx * 4;

    for (int j0 = start; j0 < end; j0 += 64) {
        __syncthreads();   // BufA + P free (prev PV / softmax reads done)

        // ---- load K tile via cp.async (pre-split bf16) ----
        #pragma unroll
        for (int it = 0; it < 4; ++it) {
            const int e = tid + it * 256;
            const int r = e >> 4, c = e & 15;
            const size_t gsrc = (size_t)(j0 + r) * D_MODEL + h * D_HEAD + c * 8;
            cp16(sKh + r * 272 + c * 16, &g_kh[gsrc]);
            cp16(sKl + r * 272 + c * 16, &g_kl[gsrc]);
        }
        CP_COMMIT();
        CP_WAIT0();        // K (and first-iter Q) complete, this thread
        __syncthreads();   // visible to all threads

        // ---- S = Q K^T (3-pass HMMA), warp tile 16x32 ----
        float sacc[4][4];
        #pragma unroll
        for (int nf = 0; nf < 4; ++nf)
            #pragma unroll
            for (int k = 0; k < 4; ++k) sacc[nf][k] = 0.f;

        #pragma unroll
        for (int ks = 0; ks < 8; ++ks) {
            const uint32_t off = ks * 32;
            uint32_t ah[4], al[4], bh[2][4], bl[2][4];
            ldsm_x4(ah, aQh + off);
            ldsm_x4(al, aQl + off);
            ldsm_x4(bh[0], aK0h + off);
            ldsm_x4(bh[1], aK0h + 16 * 272 + off);
            ldsm_x4(bl[0], aK0l + off);
            ldsm_x4(bl[1], aK0l + 16 * 272 + off);
            #pragma unroll
            for (int nb = 0; nb < 2; ++nb) {
                #pragma unroll
                for (int half = 0; half < 2; ++half) {
                    const int nf = nb * 2 + half;
                    mma_bf16(sacc[nf], ah, bh[nb][half], bh[nb][half + 2]);
                    mma_bf16(sacc[nf], ah, bl[nb][half], bl[nb][half + 2]);
                    mma_bf16(sacc[nf], al, bh[nb][half], bh[nb][half + 2]);
                }
            }
        }
        __syncthreads();   // all warps done reading K; BufA reusable as Sf

        // ---- store scaled S to smem ----
        #pragma unroll
        for (int nf = 0; nf < 4; ++nf) {
            const int col = wn * 32 + nf * 8 + ccol0;
            float2 v0, v1;
            v0.x = sacc[nf][0] * SM_SCALE; v0.y = sacc[nf][1] * SM_SCALE;
            v1.x = sacc[nf][2] * SM_SCALE; v1.y = sacc[nf][3] * SM_SCALE;
            *(float2*)&S.A.Sf[crow * AS_STRIDE + col]       = v0;
            *(float2*)&S.A.Sf[(crow + 8) * AS_STRIDE + col] = v1;
        }
        __syncthreads();

        // ---- online softmax (16-thread row groups) ----
        float s4[4][4];
        #pragma unroll
        for (int i = 0; i < 4; ++i) {
            const float4 sv = *(const float4*)&S.A.Sf[(r0 + i) * AS_STRIDE + c0];
            s4[i][0] = sv.x; s4[i][1] = sv.y; s4[i][2] = sv.z; s4[i][3] = sv.w;
        }
        float rmax[4];
        #pragma unroll
        for (int i = 0; i < 4; ++i) {
            float v = fmaxf(fmaxf(s4[i][0], s4[i][1]), fmaxf(s4[i][2], s4[i][3]));
            #pragma unroll
            for (int off = 8; off > 0; off >>= 1)
                v = fmaxf(v, __shfl_xor_sync(0xffffffffu, v, off));
            rmax[i] = v;
        }
        if (tx == 0) {
            #pragma unroll
            for (int i = 0; i < 4; ++i) {
                const float mo = S.m[r0 + i];
                const float mn = fmaxf(mo, rmax[i]);
                S.newm[r0 + i] = mn;
                S.cf[r0 + i]   = __expf(mo - mn);
                S.m[r0 + i]    = mn;
            }
        }
        __syncthreads();

        float rs[4];
        #pragma unroll
        for (int i = 0; i < 4; ++i) {
            const float mn = S.newm[r0 + i];
            #pragma unroll
            for (int j = 0; j < 4; ++j) s4[i][j] = __expf(s4[i][j] - mn);
            rs[i] = (s4[i][0] + s4[i][1]) + (s4[i][2] + s4[i][3]);
            #pragma unroll
            for (int off = 8; off > 0; off >>= 1)
                rs[i] += __shfl_xor_sync(0xffffffffu, rs[i], off);
        }
        if (tx == 0) {
            #pragma unroll
            for (int i = 0; i < 4; ++i)
                S.l[r0 + i] = S.l[r0 + i] * S.cf[r0 + i] + rs[i];
        }
        // write P hi/lo
        #pragma unroll
        for (int i = 0; i < 4; ++i) {
            __nv_bfloat16 h0 = __float2bfloat16(s4[i][0]);
            __nv_bfloat16 h1 = __float2bfloat16(s4[i][1]);
            __nv_bfloat16 h2 = __float2bfloat16(s4[i][2]);
            __nv_bfloat16 h3 = __float2bfloat16(s4[i][3]);
            __nv_bfloat162 hp0; hp0.x = h0; hp0.y = h1;
            __nv_bfloat162 hp1; hp1.x = h2; hp1.y = h3;
            __nv_bfloat162 lp0, lp1;
            lp0.x = __float2bfloat16(s4[i][0] - __bfloat162float(h0));
            lp0.y = __float2bfloat16(s4[i][1] - __bfloat162float(h1));
            lp1.x = __float2bfloat16(s4[i][2] - __bfloat162float(h2));
            lp1.y = __float2bfloat16(s4[i][3] - __bfloat162float(h3));
            *(__nv_bfloat162*)&S.Ph[(r0 + i) * AV_STRIDE + c0]     = hp0;
            *(__nv_bfloat162*)&S.Ph[(r0 + i) * AV_STRIDE + c0 + 2] = hp1;
            *(__nv_bfloat162*)&S.Pl[(r0 + i) * AV_STRIDE + c0]     = lp0;
            *(__nv_bfloat162*)&S.Pl[(r0 + i) * AV_STRIDE + c0 + 2] = lp1;
        }
        __syncthreads();   // Sf reads done; stats/P visible; BufA -> V

        // ---- load V tile transposed (V^T[d][j]), split hi/lo ----
        #pragma unroll 4
        for (int it = 0; it < 32; ++it) {
            const int e = tid + it * 256;
            const int d = e & 127, j = e >> 7;
            const float v = g_qkv[(size_t)(j0 + j) * QKV_COLS + 2 * D_MODEL + h * D_HEAD + d];
            const __nv_bfloat16 hv = __float2bfloat16(v);
            S.A.V.h[d * AV_STRIDE + j] = hv;
            S.A.V.l[d * AV_STRIDE + j] = __float2bfloat16(v - __bfloat162float(hv));
        }
        // rescale O by cf
        {
            const float cf1 = S.cf[crow];
            const float cf2 = S.cf[crow + 8];
            #pragma unroll
            for (int nf = 0; nf < 8; ++nf) {
                o[nf][0] *= cf1; o[nf][1] *= cf1;
                o[nf][2] *= cf2; o[nf][3] *= cf2;
            }
        }
        __syncthreads();

        // ---- O += P V (3-pass HMMA), warp tile 16x64 ----
        #pragma unroll
        for (int ks = 0; ks < 4; ++ks) {
            const uint32_t off = ks * 32;
            uint32_t pah[4], pal[4];
            ldsm_x4(pah, aPh + off);
            ldsm_x4(pal, aPl + off);
            #pragma unroll
            for (int nb = 0; nb < 4; ++nb) {
                uint32_t vh[4], vl[4];
                ldsm_x4(vh, aVhB + nb * 16 * 144 + off);
                ldsm_x4(vl, aVlB + nb * 16 * 144 + off);
                #pragma unroll
                for (int half = 0; half < 2; ++half) {
                    const int nf = nb * 2 + half;
                    mma_bf16(o[nf], pah, vh[half], vh[half + 2]);
                    mma_bf16(o[nf], pah, vl[half], vl[half + 2]);
                    mma_bf16(o[nf], pal, vh[half], vh[half + 2]);
                }
            }
        }
    }

    // ---- epilogue: normalize, split hi/lo, store to g_ahi/g_alo ----
    const float linv1 = 1.f / S.l[crow];
    const float linv2 = 1.f / S.l[crow + 8];
    const int gr1 = q0 + crow, gr2 = q0 + crow + 8;
    #pragma unroll
    for (int nf = 0; nf < 8; ++nf) {
        const int col = h * D_HEAD + wn * 64 + nf * 8 + ccol0;
        float v0 = o[nf][0] * linv1, v1 = o[nf][1] * linv1;
        float v2 = o[nf][2] * linv2, v3 = o[nf][3] * linv2;
        __nv_bfloat16 h0 = __float2bfloat16(v0), h1 = __float2bfloat16(v1);
        __nv_bfloat16 h2 = __float2bfloat16(v2), h3 = __float2bfloat16(v3);
        __nv_bfloat162 hp0; hp0.x = h0; hp0.y = h1;
        __nv_bfloat162 hp1; hp1.x = h2; hp1.y = h3;
        __nv_bfloat162 lp0, lp1;
        lp0.x = __float2bfloat16(v0 - __bfloat162float(h0));
        lp0.y = __float2bfloat16(v1 - __bfloat162float(h1));
        lp1.x = __float2bfloat16(v2 - __bfloat162float(h2));
        lp1.y = __float2bfloat16(v3 - __bfloat162float(h3));
        *(__nv_bfloat162*)&g_ahi[(size_t)gr1 * D_MODEL + col] = hp0;
        *(__nv_bfloat162*)&g_alo[(size_t)gr1 * D_MODEL + col] = lp0;
        *(__nv_bfloat162*)&g_ahi[(size_t)gr2 * D_MODEL + col] = hp1;
        *(__nv_bfloat162*)&g_alo[(size_t)gr2 * D_MODEL + col] = lp1;
    }
}

// ---------------------------------------------------------------------------
extern "C" void kernel_launch(void* const* d_in, const int* in_sizes, int n_in,
                              void* d_out, int out_size)
{
    const float* x        = (const float*)d_in[0];
    const float* pe       = (const float*)d_in[1];
    const int*   seq_lens = (const int*)  d_in[2];
    const float* qkv_w    = (const float*)d_in[3];
    const float* qkv_b    = (const float*)d_in[4];
    const float* q_scale  = (const float*)d_in[5];
    const float* k_scale  = (const float*)d_in[6];
    const float* proj_w   = (const float*)d_in[7];
    const float* proj_b   = (const float*)d_in[8];
    float* out = (float*)d_out;

    float *qkv_ptr = nullptr;
    __nv_bfloat16 *xhi, *xlo, *wqh, *wql, *wph, *wpl, *ahi, *alo;
    cudaGetSymbolAddress((void**)&qkv_ptr,  g_qkv);
    cudaGetSymbolAddress((void**)&xhi, g_xhi);
    cudaGetSymbolAddress((void**)&xlo, g_xlo);
    cudaGetSymbolAddress((void**)&wqh, g_wqkv_hi);
    cudaGetSymbolAddress((void**)&wql, g_wqkv_lo);
    cudaGetSymbolAddress((void**)&wph, g_wp_hi);
    cudaGetSymbolAddress((void**)&wpl, g_wp_lo);
    cudaGetSymbolAddress((void**)&ahi, g_ahi);
    cudaGetSymbolAddress((void**)&alo, g_alo);

    const int attn_smem = (int)sizeof(AttnSmem);
    cudaFuncSetAttribute(attn_mma_kernel,
                         cudaFuncAttributeMaxDynamicSharedMemorySize, attn_smem);
    cudaFuncSetAttribute(gemm_mma,
                         cudaFuncAttributeMaxDynamicSharedMemorySize, GEMM_SMEM);

    // 0) split inputs into bf16 hi/lo
    {
        const int n4x = (L_TOTAL * D_MODEL) / 4;      // 1M
        const int n4w = (QKV_COLS * D_MODEL) / 4;     // 3M
        split_bf16_kernel<<<n4x / 256, 256>>>(x, xhi, xlo, n4x);
        split_bf16_kernel<<<n4w / 256, 256>>>(qkv_w, wqh, wql, n4w);
        split_bf16_kernel<<<n4x / 256, 256>>>(proj_w, wph, wpl, n4x);
    }

    // 1) qkv = x @ qkv_w^T + qkv_b   (HMMA, split-bf16 3-pass, 2-stage async)
    gemm_mma<<<dim3(QKV_COLS / 128, L_TOTAL / 128), 256, GEMM_SMEM>>>(
        xhi, xlo, wqh, wql, qkv_b, qkv_ptr, QKV_COLS, D_MODEL);

    // 2) RMSNorm + RoPE: q,k -> split bf16 globals (v stays fp32 in g_qkv)
    norm_rope_kernel<<<dim3(L_TOTAL, 2 * N_HEADS), 128>>>(pe, q_scale, k_scale);

    // 3) block-diagonal flash attention (HMMA) -> g_ahi/g_alo directly
    attn_mma_kernel<<<dim3(L_TOTAL / 64, N_HEADS), 256, attn_smem>>>(seq_lens);

    // 4) out = attn @ proj_w^T + proj_b
    gemm_mma<<<dim3(D_MODEL / 128, L_TOTAL / 128), 256, GEMM_SMEM>>>(
        ahi, alo, wph, wpl, proj_b, out, D_MODEL, D_MODEL);
}